// round 1
// baseline (speedup 1.0000x reference)
#include <cuda_runtime.h>
#include <stdint.h>

// PowderWorld one-step update, restructured as:
//   1) extract per-cell element id (byte) from one-hot channels 1..13
//   2) build state byte: id | grav<<4 | didgrav<<5 | falldir<<6
//      (stone gravity rule uses zero-padded diagonal-above neighbors)
//   3) 8 swap passes (4 vertical gravity, 4 diagonal) on the 2MB state grid
//      (all roll-based => wraparound). Masks are disjoint pairwise swaps, so
//      whole-cell-vector permutation == permutation of (id,grav) state.
//      didgrav and falldir bits are position-fixed (never swapped).
//   4) synthesize full 20-channel output from final state byte
//      (c<14 one-hot, c14=density, c15=grav, c16..19=0).

#define BATCH 8
#define H 512
#define W 512
#define CH 20
#define HW (H * W)
#define NCELL (BATCH * HW)

__constant__ uint8_t c_dens[16] = {1,4,3,2,0,4,4,0,4,3,3,2,3,4,0,0};
__constant__ uint8_t c_grav[16] = {1,0,1,1,1,0,0,1,0,1,1,1,1,0,0,0};

__device__ uint8_t g_id[NCELL];
__device__ uint8_t g_state[2][NCELL];

// ---------------------------------------------------------------- id extract
__global__ void k_extract_id(const float* __restrict__ world) {
    int t = blockIdx.x * blockDim.x + threadIdx.x;     // one thread per 4 cells
    int cell = t * 4;
    int b = cell >> 18;                                 // / HW
    int rem = cell & (HW - 1);
    const float* base = world + (size_t)b * CH * HW + rem;
    float a0 = 0.f, a1 = 0.f, a2 = 0.f, a3 = 0.f;
#pragma unroll
    for (int e = 1; e < 14; e++) {
        float4 v = *reinterpret_cast<const float4*>(base + (size_t)e * HW);
        a0 += (float)e * v.x; a1 += (float)e * v.y;
        a2 += (float)e * v.z; a3 += (float)e * v.w;
    }
    uchar4 o;
    o.x = (uint8_t)(a0 + 0.5f);
    o.y = (uint8_t)(a1 + 0.5f);
    o.z = (uint8_t)(a2 + 0.5f);
    o.w = (uint8_t)(a3 + 0.5f);
    *reinterpret_cast<uchar4*>(g_id + cell) = o;
}

// ---------------------------------------------------------------- state init
// grav: stone (id==9) cells get grav = (diag-above supports < 2), zero-padded
// borders (reference uses jnp.pad here, NOT roll). Others get table gravity.
__global__ void k_init_state(const float* __restrict__ rnd) {
    int cell = blockIdx.x * blockDim.x + threadIdx.x;
    int rem = cell & (HW - 1);
    int i = rem >> 9;
    int j = rem & (W - 1);
    uint8_t id = g_id[cell];
    int grav;
    if (id == 9) {
        int sup = 0;
        if (i > 0) {
            if (j > 0)     sup += (g_id[cell - W - 1] == 9);
            if (j < W - 1) sup += (g_id[cell - W + 1] == 9);
        }
        grav = (sup < 2) ? 1 : 0;
    } else {
        grav = c_grav[id];
    }
    int fall = (rnd[cell] > 0.5f) ? 1 : 0;
    g_state[0][cell] = (uint8_t)(id | (grav << 4) | (fall << 6));
}

// ---------------------------------------------------------------- gravity
// become_below[i] = (d[i]==curr) & (d[i]>d[i+1]) & g[i] & g[i+1]  -> take i+1
// become_above[i] = (d[i-1]==curr) & (d[i-1]>d[i]) & g[i] & g[i-1]-> take i-1
// didgrav |= become_above (position-fixed bit 5). Wraparound (jnp.roll).
__global__ void k_gravity(int curr, int sidx) {
    int cell = blockIdx.x * blockDim.x + threadIdx.x;
    const uint8_t* __restrict__ src = g_state[sidx];
    uint8_t* __restrict__ dst = g_state[sidx ^ 1];
    int rem = cell & (HW - 1);
    int i = rem >> 9;
    int up = (i == 0)     ? cell + (H - 1) * W : cell - W;
    int dn = (i == H - 1) ? cell - (H - 1) * W : cell + W;
    uint8_t sc = src[cell], sa = src[up], sb = src[dn];
    int d  = c_dens[sc & 15], da = c_dens[sa & 15], db = c_dens[sb & 15];
    int g  = (sc >> 4) & 1, ga = (sa >> 4) & 1, gb = (sb >> 4) & 1;
    bool below = (d == curr)  && (d > db)  && g && gb;
    bool above = (da == curr) && (da > d)  && g && ga;
    uint8_t moved = below ? (uint8_t)(sb & 0x1F)
                  : above ? (uint8_t)(sa & 0x1F)
                          : (uint8_t)(sc & 0x1F);
    dst[cell] = (uint8_t)(moved | (sc & 0x60) | (above ? 0x20 : 0));
}

// ---------------------------------------------------------------- diagonal
// fall_left:  bl = (i+1, j-1), ar = (i-1, j+1), matching = fall bit
// fall_right: bl = (i+1, j+1), ar = (i-1, j-1), matching = !fall bit
// become_bl: id==elem & ndg & ndg_bl & match & (d > d_bl) & g & g_bl -> take bl
// become_ar: id_ar==elem & ndg & ndg_ar & match_ar & (d_ar > d) & g & g_ar -> take ar
__global__ void k_diag(int elem, int fall_left, int sidx) {
    int cell = blockIdx.x * blockDim.x + threadIdx.x;
    const uint8_t* __restrict__ src = g_state[sidx];
    uint8_t* __restrict__ dst = g_state[sidx ^ 1];
    int rem = cell & (HW - 1);
    int i = rem >> 9;
    int j = rem & (W - 1);
    int base = cell - rem;                      // b * HW
    int ip = (i + 1) & (H - 1);
    int im = (i - 1) & (H - 1);
    int jp = (j + 1) & (W - 1);
    int jm = (j - 1) & (W - 1);
    int jbl = fall_left ? jm : jp;
    int jar = fall_left ? jp : jm;
    uint8_t sc  = src[cell];
    uint8_t sbl = src[base + ip * W + jbl];
    uint8_t sar = src[base + im * W + jar];
    int d   = c_dens[sc & 15], dbl = c_dens[sbl & 15], dar = c_dens[sar & 15];
    int g   = (sc >> 4) & 1, gbl = (sbl >> 4) & 1, gar = (sar >> 4) & 1;
    int f   = (sc >> 6) & 1, fa  = (sar >> 6) & 1;
    int mf   = fall_left ? f  : (1 - f);
    int mfar = fall_left ? fa : (1 - fa);
    int ndg   = 1 - ((sc  >> 5) & 1);
    int ndgbl = 1 - ((sbl >> 5) & 1);
    int ndgar = 1 - ((sar >> 5) & 1);
    bool bbl = ((sc & 15) == elem)  && ndg && ndgbl && mf   && (d > dbl)  && g && gbl;
    bool bar = ((sar & 15) == elem) && ndg && ndgar && mfar && (dar > d)  && g && gar;
    uint8_t moved = bbl ? (uint8_t)(sbl & 0x1F)
                  : bar ? (uint8_t)(sar & 0x1F)
                        : (uint8_t)(sc & 0x1F);
    dst[cell] = (uint8_t)(moved | (sc & 0x60));
}

// ---------------------------------------------------------------- output
__global__ void k_write_out(float* __restrict__ out, int sidx) {
    int t = blockIdx.x * blockDim.x + threadIdx.x;     // one thread per 4 cells
    int cell = t * 4;
    int b = cell >> 18;
    int rem = cell & (HW - 1);
    uchar4 s4 = *reinterpret_cast<const uchar4*>(g_state[sidx] + cell);
    uint8_t st[4] = {s4.x, s4.y, s4.z, s4.w};
    float* base = out + (size_t)b * CH * HW + rem;
#pragma unroll
    for (int c = 0; c < CH; c++) {
        float4 v;
        float vv[4];
#pragma unroll
        for (int k = 0; k < 4; k++) {
            int id = st[k] & 15;
            float x;
            if (c < 14)       x = (id == c) ? 1.0f : 0.0f;
            else if (c == 14) x = (float)c_dens[id];
            else if (c == 15) x = (float)((st[k] >> 4) & 1);
            else              x = 0.0f;
            vv[k] = x;
        }
        v.x = vv[0]; v.y = vv[1]; v.z = vv[2]; v.w = vv[3];
        *reinterpret_cast<float4*>(base + (size_t)c * HW) = v;
    }
}

// ---------------------------------------------------------------- launch
extern "C" void kernel_launch(void* const* d_in, const int* in_sizes, int n_in,
                              void* d_out, int out_size) {
    const float* world = (const float*)d_in[0];
    const float* rnd   = (const float*)d_in[1];
    float* out = (float*)d_out;
    (void)in_sizes; (void)n_in; (void)out_size;

    const int TPB = 256;
    k_extract_id<<<(NCELL / 4) / TPB, TPB>>>(world);
    k_init_state<<<NCELL / TPB, TPB>>>(rnd);

    int s = 0;
    for (int curr = 0; curr < 4; curr++) {
        k_gravity<<<NCELL / TPB, TPB>>>(curr, s);
        s ^= 1;
    }
    const int elems[2] = {2, 12};
    for (int ei = 0; ei < 2; ei++) {
        for (int fl = 1; fl >= 0; fl--) {   // True (left) then False (right)
            k_diag<<<NCELL / TPB, TPB>>>(elems[ei], fl, s);
            s ^= 1;
        }
    }
    k_write_out<<<(NCELL / 4) / TPB, TPB>>>(out, s);
}

// round 5
// speedup vs baseline: 1.7062x; 1.7062x over previous
#include <cuda_runtime.h>
#include <stdint.h>

// PowderWorld one-step update.
//   Kernel 1: extract per-cell element id (byte) from one-hot channels 1..13.
//   Kernel 2 (fused): per 64x64 tile with halo 8 in SMEM:
//       - init state byte: id | grav<<4 | didgrav<<5 | fall<<6
//         (stone gravity uses zero-padded diag-above neighbors, true coords)
//       - 4 vertical gravity passes + 4 diagonal passes, all roll(wrap)-based,
//         valid window shrinks by 1 per pass; final 64x64 interior exact.
//   Kernel 3: synthesize 20-channel float output from final state byte.
// All table lookups are packed-register constants (no indexed __constant__).

#define NB 8
#define H 512
#define W 512
#define CH 20
#define HW (H * W)
#define NCELL (NB * HW)

#define RAD 8
#define TT 64            // interior tile
#define LL 80            // TT + 2*RAD
#define LP 84            // smem pitch for state tiles
#define LI 82            // id tile (state region + 1 ring)

#define DENS64 0x0043233404402341ULL   // dens[id] nibbles, id=0..15
#define GRAV16 0x1E9Du                 // grav[id] bits,   id=0..15

__device__ uint8_t g_id[NCELL];
__device__ uint8_t g_fin[NCELL];

__device__ __forceinline__ uint32_t dens_of(uint32_t s) {
    return (uint32_t)(DENS64 >> ((s & 15u) * 4u)) & 7u;
}

// ---------------------------------------------------------------- id extract
__global__ void k_extract_id(const float* __restrict__ world) {
    int t = blockIdx.x * blockDim.x + threadIdx.x;   // one thread per 4 cells
    int cell = t * 4;
    int b = cell >> 18;
    int rem = cell & (HW - 1);
    const float* base = world + (size_t)b * CH * HW + rem;
    float a0 = 0.f, a1 = 0.f, a2 = 0.f, a3 = 0.f;
#pragma unroll
    for (int e = 1; e < 14; e++) {
        float4 v = *reinterpret_cast<const float4*>(base + (size_t)e * HW);
        a0 += (float)e * v.x; a1 += (float)e * v.y;
        a2 += (float)e * v.z; a3 += (float)e * v.w;
    }
    uchar4 o;
    o.x = (uint8_t)(a0 + 0.5f);
    o.y = (uint8_t)(a1 + 0.5f);
    o.z = (uint8_t)(a2 + 0.5f);
    o.w = (uint8_t)(a3 + 0.5f);
    *reinterpret_cast<uchar4*>(g_id + cell) = o;
}

// ---------------------------------------------------------------- passes
__device__ __forceinline__ void do_grav(uint8_t (&S)[LL][LP], uint8_t (&D)[LL][LP],
                                        uint32_t curr, int lo, int hi, int ty, int tx) {
    for (int y = lo + ty; y < hi; y += 4) {
#pragma unroll
        for (int k = 0; k < 2; k++) {
            int x = lo + tx + k * 64;
            if (x < hi) {
                uint32_t sc = S[y][x], sa = S[y - 1][x], sb = S[y + 1][x];
                uint32_t d = dens_of(sc), da = dens_of(sa), db = dens_of(sb);
                bool g  = (sc & 16u) != 0;
                bool ga = (sa & 16u) != 0;
                bool gb = (sb & 16u) != 0;
                bool below = (d == curr)  & (d > db) & g & gb;
                bool above = (da == curr) & (da > d) & g & ga;
                uint32_t moved = below ? (sb & 0x1Fu)
                               : above ? (sa & 0x1Fu)
                                       : (sc & 0x1Fu);
                D[y][x] = (uint8_t)(moved | (sc & 0x60u) | (above ? 0x20u : 0u));
            }
        }
    }
}

__device__ __forceinline__ void do_diag(uint8_t (&S)[LL][LP], uint8_t (&D)[LL][LP],
                                        uint32_t elem, int fl, int lo, int hi,
                                        int ty, int tx) {
    for (int y = lo + ty; y < hi; y += 4) {
#pragma unroll
        for (int k = 0; k < 2; k++) {
            int x = lo + tx + k * 64;
            if (x < hi) {
                int xb = fl ? x - 1 : x + 1;   // below-lateral column
                int xa = fl ? x + 1 : x - 1;   // above-reverse column
                uint32_t sc  = S[y][x];
                uint32_t sbl = S[y + 1][xb];
                uint32_t sar = S[y - 1][xa];
                uint32_t d = dens_of(sc), dbl = dens_of(sbl), dar = dens_of(sar);
                bool g   = (sc  & 16u) != 0;
                bool gbl = (sbl & 16u) != 0;
                bool gar = (sar & 16u) != 0;
                bool f   = (sc  & 64u) != 0;
                bool fa  = (sar & 64u) != 0;
                bool mf  = fl ? f  : !f;
                bool mfa = fl ? fa : !fa;
                bool ndg   = (sc  & 32u) == 0;
                bool ndgbl = (sbl & 32u) == 0;
                bool ndgar = (sar & 32u) == 0;
                bool bbl = ((sc  & 15u) == elem) & ndg & ndgbl & mf  & (d > dbl)  & g & gbl;
                bool bar = ((sar & 15u) == elem) & ndg & ndgar & mfa & (dar > d)  & g & gar;
                uint32_t moved = bbl ? (sbl & 0x1Fu)
                               : bar ? (sar & 0x1Fu)
                                     : (sc & 0x1Fu);
                D[y][x] = (uint8_t)(moved | (sc & 0x60u));
            }
        }
    }
}

// ---------------------------------------------------------------- fused sim
__global__ void __launch_bounds__(256) k_fused(const float* __restrict__ rnd) {
    __shared__ uint8_t sid[LI][LI];
    __shared__ uint8_t sA[LL][LP];
    __shared__ uint8_t sB[LL][LP];

    int tid = threadIdx.x;
    int tx = tid & 63, ty = tid >> 6;
    int X0 = blockIdx.x * TT, Y0 = blockIdx.y * TT;
    int b = blockIdx.z;
    const uint8_t* idb = g_id + (size_t)b * HW;

    // load id tile (state region + 1 ring), wrap indexing (roll semantics)
    for (int idx = tid; idx < LI * LI; idx += 256) {
        int ly = idx / LI, lx = idx - ly * LI;
        int gy = (Y0 - RAD - 1 + ly) & (H - 1);
        int gx = (X0 - RAD - 1 + lx) & (W - 1);
        sid[ly][lx] = idb[gy * W + gx];
    }
    __syncthreads();

    // init state for 80x80 region
    const float* rb = rnd + (size_t)b * HW;
    for (int idx = tid; idx < LL * LL; idx += 256) {
        int sy = idx / LL, sx = idx - sy * LL;
        int gy = (Y0 - RAD + sy) & (H - 1);
        int gx = (X0 - RAD + sx) & (W - 1);
        uint32_t id = sid[sy + 1][sx + 1];
        uint32_t grav;
        if (id == 9u) {
            int sup = 0;
            if (gy > 0) {                       // zero-pad at true grid border
                if (gx > 0)     sup += (sid[sy][sx]     == 9u);
                if (gx < W - 1) sup += (sid[sy][sx + 2] == 9u);
            }
            grav = (sup < 2) ? 1u : 0u;
        } else {
            grav = (GRAV16 >> id) & 1u;
        }
        uint32_t fall = (rb[gy * W + gx] > 0.5f) ? 1u : 0u;
        sA[sy][sx] = (uint8_t)(id | (grav << 4) | (fall << 6));
    }
    __syncthreads();

    // 4 gravity passes (curr density 0..3)
    do_grav(sA, sB, 0u, 1, 79, ty, tx); __syncthreads();
    do_grav(sB, sA, 1u, 2, 78, ty, tx); __syncthreads();
    do_grav(sA, sB, 2u, 3, 77, ty, tx); __syncthreads();
    do_grav(sB, sA, 3u, 4, 76, ty, tx); __syncthreads();
    // 4 diagonal passes: elem 2 (left,right), elem 12 (left,right)
    do_diag(sA, sB, 2u,  1, 5, 75, ty, tx); __syncthreads();
    do_diag(sB, sA, 2u,  0, 6, 74, ty, tx); __syncthreads();
    do_diag(sA, sB, 12u, 1, 7, 73, ty, tx); __syncthreads();
    do_diag(sB, sA, 12u, 0, 8, 72, ty, tx); __syncthreads();

    // write final 64x64 interior
    uint8_t* fb = g_fin + (size_t)b * HW;
    for (int idx = tid; idx < TT * TT; idx += 256) {
        int iy = idx >> 6, ix = idx & 63;
        fb[(Y0 + iy) * W + X0 + ix] = sA[RAD + iy][RAD + ix];
    }
}

// ---------------------------------------------------------------- output
__global__ void k_write_out(float* __restrict__ out) {
    int t = blockIdx.x * blockDim.x + threadIdx.x;   // one thread per 4 cells
    int cell = t * 4;
    int b = cell >> 18;
    int rem = cell & (HW - 1);
    uchar4 s4 = *reinterpret_cast<const uchar4*>(g_fin + cell);
    uint8_t st[4] = {s4.x, s4.y, s4.z, s4.w};
    float* base = out + (size_t)b * CH * HW + rem;
#pragma unroll
    for (int c = 0; c < CH; c++) {
        float4 v;
        float vv[4];
#pragma unroll
        for (int k = 0; k < 4; k++) {
            uint32_t id = st[k] & 15u;
            float x;
            if (c < 14)       x = (id == (uint32_t)c) ? 1.0f : 0.0f;
            else if (c == 14) x = (float)((uint32_t)(DENS64 >> (id * 4u)) & 7u);
            else if (c == 15) x = (float)((st[k] >> 4) & 1u);
            else              x = 0.0f;
            vv[k] = x;
        }
        v.x = vv[0]; v.y = vv[1]; v.z = vv[2]; v.w = vv[3];
        *reinterpret_cast<float4*>(base + (size_t)c * HW) = v;
    }
}

// ---------------------------------------------------------------- launch
extern "C" void kernel_launch(void* const* d_in, const int* in_sizes, int n_in,
                              void* d_out, int out_size) {
    const float* world = (const float*)d_in[0];
    const float* rnd   = (const float*)d_in[1];
    float* out = (float*)d_out;
    (void)in_sizes; (void)n_in; (void)out_size;

    const int TPB = 256;
    k_extract_id<<<(NCELL / 4) / TPB, TPB>>>(world);
    dim3 g(H / TT, H / TT, NB);          // 8 x 8 x 8 = 512 tiles
    k_fused<<<g, TPB>>>(rnd);
    k_write_out<<<(NCELL / 4) / TPB, TPB>>>(out);
}

// round 16
// speedup vs baseline: 2.0672x; 1.2115x over previous
#include <cuda_runtime.h>
#include <stdint.h>

// PowderWorld one-step update, SWAR edition.
//   K1: extract per-cell element id (byte) from one-hot channels 1..13 (8 cells/thread).
//   K2 (fused): 64x64 tile + halo 8; state packed 4 cells per uint32 word.
//       8 passes on SMEM word tiles; per-byte logic done SWAR (PRMT density LUT,
//       carry-free byte compares). Valid window shrinks 1/pass; interior exact.
//   K3: synthesize 20-channel float output from final state byte.

#define NB 8
#define H 512
#define W 512
#define CH 20
#define HW (H * W)
#define NCELL (NB * HW)

#define RAD 8
#define TT 64
#define LL 80
#define WPITCH 23        // u32 words per tile row: col0 guard, 1..20 data, 21 guard, 22 pad
#define NW 20

#define DENS64 0x0043233404402341ULL   // dens[id] nibbles
#define GRAV16 0x1E9Du                 // grav[id] bits
#define M1  0x01010101u
#define TL0 0x02030401u   // dens ids 0-3  = 1,4,3,2
#define TL1 0x00040400u   // dens ids 4-7  = 0,4,4,0
#define TH0 0x02030304u   // dens ids 8-11 = 4,3,3,2
#define TH1 0x00000403u   // dens ids 12-15= 3,4,0,0

__device__ uint8_t g_id[NCELL];
__device__ uint8_t g_fin[NCELL];

// per-byte density (0..4) of a packed state word
__device__ __forceinline__ uint32_t densw(uint32_t w) {
    uint32_t x = w & 0x07070707u;
    uint32_t sel = x | (x >> 12);                 // nibbles [c0,c2,c1,c3]
    uint32_t dpl = __byte_perm(TL0, TL1, sel);
    uint32_t dph = __byte_perm(TH0, TH1, sel);
    uint32_t m = (w >> 3) & M1;                   // id bit3 per byte
    uint32_t mask = (m << 8) - m;                 // 0xFF per hi-id byte
    uint32_t maskp = __byte_perm(mask, mask, 0x3120);
    uint32_t dp = (dph & maskp) | (dpl & ~maskp); // dens, permuted [c0,c2,c1,c3]
    return __byte_perm(dp, dp, 0x3120);           // unpermute
}
// 1 at bit0 of each byte whose value is 0 (requires bytes <= 0x80)
__device__ __forceinline__ uint32_t zero01(uint32_t x) {
    uint32_t t = x + 0x7F7F7F7Fu;
    return (~t & 0x80808080u) >> 7;
}
// 1 at bit0 of each byte where p > q (bytes of p,q <= 7; t = p-q+7, bit3 iff p>q)
__device__ __forceinline__ uint32_t gt01(uint32_t p, uint32_t q) {
    uint32_t t = p + (0x07070707u - q);
    return (t >> 3) & M1;
}
// expand 0/1 bytes to 0x00/0xFF bytes
__device__ __forceinline__ uint32_t bmask(uint32_t b) { return (b << 8) - b; }

// ---------------------------------------------------------------- id extract
__global__ void k_extract_id(const float* __restrict__ world) {
    int t = blockIdx.x * blockDim.x + threadIdx.x;   // one thread per 8 cells
    int cell = t * 8;
    int b = cell >> 18;
    int rem = cell & (HW - 1);
    const float* base = world + (size_t)b * CH * HW + rem;
    float a0=0.f,a1=0.f,a2=0.f,a3=0.f,a4=0.f,a5=0.f,a6=0.f,a7=0.f;
#pragma unroll
    for (int e = 1; e < 14; e++) {
        float4 v0 = *reinterpret_cast<const float4*>(base + (size_t)e * HW);
        float4 v1 = *reinterpret_cast<const float4*>(base + (size_t)e * HW + 4);
        float fe = (float)e;
        a0 += fe * v0.x; a1 += fe * v0.y; a2 += fe * v0.z; a3 += fe * v0.w;
        a4 += fe * v1.x; a5 += fe * v1.y; a6 += fe * v1.z; a7 += fe * v1.w;
    }
    uint32_t w0 = (uint32_t)(a0+0.5f) | ((uint32_t)(a1+0.5f)<<8)
                | ((uint32_t)(a2+0.5f)<<16) | ((uint32_t)(a3+0.5f)<<24);
    uint32_t w1 = (uint32_t)(a4+0.5f) | ((uint32_t)(a5+0.5f)<<8)
                | ((uint32_t)(a6+0.5f)<<16) | ((uint32_t)(a7+0.5f)<<24);
    uint2 o; o.x = w0; o.y = w1;
    *reinterpret_cast<uint2*>(g_id + cell) = o;
}

// ---------------------------------------------------------------- SWAR passes
__device__ __forceinline__ void pass_grav(const uint32_t* __restrict__ S,
                                          uint32_t* __restrict__ D,
                                          uint32_t curr4, int tid) {
    for (int idx = tid; idx < 78 * NW; idx += 256) {
        int y = 1 + idx / NW;
        int xw = 1 + (idx - (idx / NW) * NW);
        const uint32_t* row = S + y * WPITCH + xw;
        uint32_t c = row[0], a = row[-WPITCH], b = row[WPITCH];
        uint32_t dc = densw(c), da = densw(a), db = densw(b);
        uint32_t below = zero01(dc ^ curr4) & gt01(dc, db) & (c >> 4) & (b >> 4);
        uint32_t above = zero01(da ^ curr4) & gt01(da, dc) & (c >> 4) & (a >> 4);
        below &= M1; above &= M1;
        uint32_t bm = bmask(below), am = bmask(above);
        uint32_t mov = (b & bm) | (a & am) | (c & ~(bm | am));
        D[y * WPITCH + xw] = (mov & 0x1F1F1F1Fu) | (c & 0x60606060u) | (above << 5);
    }
}

__device__ __forceinline__ void pass_diag(const uint32_t* __restrict__ S,
                                          uint32_t* __restrict__ D,
                                          uint32_t e4, int fl, int tid) {
    for (int idx = tid; idx < 78 * NW; idx += 256) {
        int y = 1 + idx / NW;
        int xw = 1 + (idx - (idx / NW) * NW);
        const uint32_t* rc = S + y * WPITCH + xw;
        uint32_t c = rc[0];
        uint32_t b0 = rc[WPITCH - 1], b1 = rc[WPITCH], b2 = rc[WPITCH + 1];
        uint32_t a0 = rc[-WPITCH - 1], a1 = rc[-WPITCH], a2 = rc[-WPITCH + 1];
        // below-lateral word (cells x-1 if fl else x+1), above-reverse word (opposite)
        uint32_t bl = fl ? __funnelshift_l(b0, b1, 8)   // (b1<<8)|(b0>>24)
                         : __funnelshift_r(b1, b2, 8);  // (b1>>8)|(b2<<24)
        uint32_t ar = fl ? __funnelshift_r(a1, a2, 8)
                         : __funnelshift_l(a0, a1, 8);
        uint32_t dc = densw(c), dbl = densw(bl), dar = densw(ar);
        uint32_t iec = zero01((c  & 0x0F0F0F0Fu) ^ e4);
        uint32_t iea = zero01((ar & 0x0F0F0F0Fu) ^ e4);
        uint32_t fc = (fl ? c : ~c) >> 6;     // matching-fall bit at bit0 (after &)
        uint32_t fa = (fl ? ar : ~ar) >> 6;
        uint32_t nc = (~c) >> 5, nbl = (~bl) >> 5, nar = (~ar) >> 5;
        uint32_t bbl = iec & gt01(dc, dbl) & fc & nc & nbl & (c >> 4) & (bl >> 4);
        uint32_t bar = iea & gt01(dar, dc) & fa & nc & nar & (c >> 4) & (ar >> 4);
        bbl &= M1; bar &= M1;
        uint32_t bm = bmask(bbl), am = bmask(bar);
        uint32_t mov = (bl & bm) | (ar & am) | (c & ~(bm | am));
        D[y * WPITCH + xw] = (mov & 0x1F1F1F1Fu) | (c & 0x60606060u);
    }
}

// ---------------------------------------------------------------- fused sim
__global__ void __launch_bounds__(256) k_fused(const float* __restrict__ rnd) {
    __shared__ uint8_t  sid[LL + 2][LL + 4];        // id tile + 1 ring, 84B pitch
    __shared__ uint32_t sW[2][LL * WPITCH];

    int tid = threadIdx.x;
    int X0 = blockIdx.x * TT, Y0 = blockIdx.y * TT;
    int b = blockIdx.z;
    const uint8_t* idb = g_id + (size_t)b * HW;

    // load id tile (82x82, wrap indexing)
    for (int idx = tid; idx < 82 * 82; idx += 256) {
        int ly = idx / 82, lx = idx - ly * 82;
        int gy = (Y0 - RAD - 1 + ly) & (H - 1);
        int gx = (X0 - RAD - 1 + lx) & (W - 1);
        sid[ly][lx] = idb[gy * W + gx];
    }
    // zero tile B (guards + stale rows determinism)
    for (int idx = tid; idx < LL * WPITCH; idx += 256) sW[1][idx] = 0;
    __syncthreads();

    // init state words for 80x80 region
    const float* rb = rnd + (size_t)b * HW;
    for (int idx = tid; idx < LL * WPITCH; idx += 256) {
        int y = idx / WPITCH;
        int col = idx - y * WPITCH;
        if (col == 0 || col >= 21) { sW[0][idx] = 0; continue; }
        int x0 = (col - 1) * 4;
        int gy = (Y0 - RAD + y) & (H - 1);
        int gx0 = (X0 - RAD + x0) & (W - 1);          // 4-aligned, group contiguous
        float4 rf = *reinterpret_cast<const float4*>(rb + gy * W + gx0);
        float rv[4] = {rf.x, rf.y, rf.z, rf.w};
        uint32_t wv = 0;
#pragma unroll
        for (int k = 0; k < 4; k++) {
            uint32_t id = sid[y + 1][x0 + 1 + k];
            uint32_t grav;
            if (id == 9u) {
                int gx = gx0 + k;
                int sup = 0;
                if (gy > 0) {
                    if (gx > 0)     sup += (sid[y][x0 + k]     == 9u);
                    if (gx < W - 1) sup += (sid[y][x0 + k + 2] == 9u);
                }
                grav = (sup < 2) ? 1u : 0u;
            } else {
                grav = (GRAV16 >> id) & 1u;
            }
            uint32_t fall = (rv[k] > 0.5f) ? 1u : 0u;
            wv |= (id | (grav << 4) | (fall << 6)) << (8 * k);
        }
        sW[0][idx] = wv;
    }
    __syncthreads();

    pass_grav(sW[0], sW[1], 0u * M1, tid); __syncthreads();
    pass_grav(sW[1], sW[0], 1u * M1, tid); __syncthreads();
    pass_grav(sW[0], sW[1], 2u * M1, tid); __syncthreads();
    pass_grav(sW[1], sW[0], 3u * M1, tid); __syncthreads();
    pass_diag(sW[0], sW[1],  2u * M1, 1, tid); __syncthreads();
    pass_diag(sW[1], sW[0],  2u * M1, 0, tid); __syncthreads();
    pass_diag(sW[0], sW[1], 12u * M1, 1, tid); __syncthreads();
    pass_diag(sW[1], sW[0], 12u * M1, 0, tid); __syncthreads();

    // write final 64x64 interior as words
    uint32_t* fb = reinterpret_cast<uint32_t*>(g_fin);
    for (int idx = tid; idx < 64 * 16; idx += 256) {
        int iy = idx >> 4, ix = idx & 15;
        uint32_t v = sW[0][(RAD + iy) * WPITCH + 3 + ix];   // col = 1 + RAD/4 + ix
        fb[((size_t)b * HW + (size_t)(Y0 + iy) * W + X0) / 4 + ix] = v;
    }
}

// ---------------------------------------------------------------- output
__global__ void k_write_out(float* __restrict__ out) {
    int t = blockIdx.x * blockDim.x + threadIdx.x;   // one thread per 4 cells
    int cell = t * 4;
    int b = cell >> 18;
    int rem = cell & (HW - 1);
    uchar4 s4 = *reinterpret_cast<const uchar4*>(g_fin + cell);
    uint8_t st[4] = {s4.x, s4.y, s4.z, s4.w};
    float* base = out + (size_t)b * CH * HW + rem;
#pragma unroll
    for (int c = 0; c < CH; c++) {
        float4 v;
        float vv[4];
#pragma unroll
        for (int k = 0; k < 4; k++) {
            uint32_t id = st[k] & 15u;
            float x;
            if (c < 14)       x = (id == (uint32_t)c) ? 1.0f : 0.0f;
            else if (c == 14) x = (float)((uint32_t)(DENS64 >> (id * 4u)) & 7u);
            else if (c == 15) x = (float)((st[k] >> 4) & 1u);
            else              x = 0.0f;
            vv[k] = x;
        }
        v.x = vv[0]; v.y = vv[1]; v.z = vv[2]; v.w = vv[3];
        *reinterpret_cast<float4*>(base + (size_t)c * HW) = v;
    }
}

// ---------------------------------------------------------------- launch
extern "C" void kernel_launch(void* const* d_in, const int* in_sizes, int n_in,
                              void* d_out, int out_size) {
    const float* world = (const float*)d_in[0];
    const float* rnd   = (const float*)d_in[1];
    float* out = (float*)d_out;
    (void)in_sizes; (void)n_in; (void)out_size;

    const int TPB = 256;
    k_extract_id<<<(NCELL / 8) / TPB, TPB>>>(world);
    dim3 g(W / TT, H / TT, NB);
    k_fused<<<g, TPB>>>(rnd);
    k_write_out<<<(NCELL / 4) / TPB, TPB>>>(out);
}